// round 14
// baseline (speedup 1.0000x reference)
#include <cuda_runtime.h>
#include <math.h>
#include <limits.h>

// WARP loss, R14: warp-per-row, depth-2 rolling scan pipeline.
// R13 kept only ONE chunk in flight during each test -> interval spacing =
// full DRAM latency; deep rows chained 16xL ~= 4.6us (the straggler tail).
// R14 rotates 3 buffers so 2 chunks are always in flight (spacing L/2),
// tests chunks with integer OR (position located only on the one hit),
// and packs 4 rows/128-thr block for a single resident wave.
// Ledger: scan ~93MB + exit-waste ~18MB + gathers ~8MB + neg 2MB.

#define FULL 0xFFFFFFFFu
#define BATCH1 16
#define CV 4                        // uint4 per lane per chunk -> 2KB chunks
#define CHUNK (CV * 32)             // 128 float4 per chunk

__device__ __forceinline__ void loadc(uint4 (&buf)[CV], const uint4* tv,
                                      int ch, int lane, int nvec) {
#pragma unroll
    for (int k = 0; k < CV; k++) {
        const int i = ch * CHUNK + k * 32 + lane;
        buf[k] = (i < nvec) ? __ldg(&tv[i]) : make_uint4(0u, 0u, 0u, 0u);
    }
}

// Returns true (warp-uniform) if the positive is in this chunk; sets pos.
__device__ __forceinline__ bool testc(const uint4 (&buf)[CV], int ch,
                                      int lane, int& pos) {
    unsigned f = 0u;
#pragma unroll
    for (int k = 0; k < CV; k++)
        f |= (buf[k].x | buf[k].y | buf[k].z | buf[k].w);
    if (!__ballot_sync(FULL, f != 0u)) return false;
    int p = INT_MAX;                      // locate (runs once per row)
#pragma unroll
    for (int k = 0; k < CV; k++) {
        const int i = ch * CHUNK + k * 32 + lane;
        if (buf[k].x) p = 4 * i;
        if (buf[k].y) p = 4 * i + 1;
        if (buf[k].z) p = 4 * i + 2;
        if (buf[k].w) p = 4 * i + 3;
    }
    pos = __reduce_min_sync(FULL, p);
    return true;
}

__global__ __launch_bounds__(128, 7)
void warp_loss_kernel(const float* __restrict__ input,
                      const float* __restrict__ target,
                      const int*   __restrict__ neg,
                      float* __restrict__ out,
                      int B, int T) {
    constexpr int Y    = 10000;
    constexpr int nvec = Y >> 2;                       // 2500 float4
    constexpr int NCH  = (nvec + CHUNK - 1) / CHUNK;   // 20 chunks

    const int gw   = blockIdx.x * 4 + (threadIdx.x >> 5);
    const int lane = threadIdx.x & 31;
    if (gw >= B) return;                               // warp-uniform

    const float* irow = input  + (size_t)gw * Y;
    const uint4* tv   = reinterpret_cast<const uint4*>(target + (size_t)gw * Y);

    // --- eager gather of first BATCH1 trials (independent of sp) ---
    int c_pre = 0;
    if (lane < BATCH1) c_pre = __ldg(&neg[(size_t)gw * T + lane]);
    const float sc_pre = __ldg(&irow[c_pre]);          // lanes>=16: bcast irow[0]

    // --- depth-2 rolling scan: 2 chunks always in flight during a test ---
    int pos = -1;
    {
        uint4 A[CV], Bb[CV], C[CV];
        loadc(A, tv, 0, lane, nvec);
        loadc(Bb, tv, 1, lane, nvec);
#pragma unroll
        for (int c = 0; c < NCH; c += 3) {
            loadc(C, tv, c + 2, lane, nvec);
            if (testc(A, c, lane, pos)) break;
            loadc(A, tv, c + 3, lane, nvec);
            if (c + 1 < NCH && testc(Bb, c + 1, lane, pos)) break;
            loadc(Bb, tv, c + 4, lane, nvec);
            if (c + 2 < NCH && testc(C, c + 2, lane, pos)) break;
        }
    }
    // scalar tail (Y % 4 != 0; empty for Y=10000) + defensive fallback
    if (pos < 0) {
        const float* trow = target + (size_t)gw * Y;
        int p = INT_MAX;
        for (int i = (nvec << 2) + lane; i < Y; i += 32)
            if (trow[i] != 0.0f) p = i;
        const int m = __reduce_min_sync(FULL, p);
        pos = (m != INT_MAX) ? m : 0;
    }

    const float sp = __ldg(&irow[pos]);                // broadcast load

    // --- first accepted among trials 0..15 (scores already in regs) ---
    const bool acc = (lane < BATCH1) && (1.0f + sc_pre - sp >= 0.0f);
    const unsigned m = __ballot_sync(FULL, acc);
    if (m) {
        const int first = __ffs(m) - 1;
        const float sn = __shfl_sync(FULL, sc_pre, first);
        if (lane == 0) {
            const int num_trials = first + 1;
            const float L = logf((float)((Y - 1) / num_trials));
            atomicAdd(out, L * (1.0f - sp + sn));
        }
    } else {
        // --- fallback (rare, ~0.3%): trials BATCH1..T-1, 32 at a time ---
        for (int t0 = BATCH1; t0 < T; t0 += 32) {
            const int t = t0 + lane;
            int c = 0;
            if (t < T) c = __ldg(&neg[(size_t)gw * T + t]);
            const float sc = __ldg(&irow[c]);
            const bool a2 = (t < T) && (1.0f + sc - sp >= 0.0f);
            const unsigned m2 = __ballot_sync(FULL, a2);
            if (m2) {
                const int fl = __ffs(m2) - 1;
                const float sn = __shfl_sync(FULL, sc, fl);
                if (lane == 0) {
                    const int num_trials = t0 + fl + 1;
                    const float L = logf((float)((Y - 1) / num_trials));
                    atomicAdd(out, L * (1.0f - sp + sn));
                }
                break;
            }
        }
    }
}

extern "C" void kernel_launch(void* const* d_in, const int* in_sizes, int n_in,
                              void* d_out, int out_size) {
    const float* input  = (const float*)d_in[0];
    const float* target = (const float*)d_in[1];
    const int*   neg    = (const int*)d_in[2];
    float* out = (float*)d_out;

    const int Y = 10000;                 // fixed by problem spec
    const int B = in_sizes[0] / Y;       // 4096
    const int T = in_sizes[2] / B;       // 128

    cudaMemsetAsync(out, 0, (size_t)out_size * sizeof(float), 0);
    warp_loss_kernel<<<(B + 3) / 4, 128>>>(input, target, neg, out, B, T);
}